// round 9
// baseline (speedup 1.0000x reference)
#include <cuda_runtime.h>
#include <stdint.h>

#define SDIM 64
#define CCH 32
#define KEYSPACE (SDIM*SDIM*SDIM*SDIM)   // 16,777,216
#define NWORDS (KEYSPACE/32)             // 524,288
#define SCAN_TPB 1024
#define SCAN_TILES (NWORDS / SCAN_TPB)   // 512
#define NMAX (1<<20)

// All state is zero-initialized at module load and restored to zero by the
// kernels that consume it, so every graph replay starts clean with no
// dedicated zeroing launch.
__device__ unsigned int g_bitmap[NWORDS];
__device__ unsigned int g_dup[NWORDS];
__device__ uint4        g_meta[NWORDS];     // {bitmap, wordpfx, dup, 0}
__device__ unsigned int g_keys[NMAX];
__device__ unsigned int g_extras;           // n - unique
__device__ unsigned int g_tilecounter;
__device__ volatile unsigned long long g_tilestate[SCAN_TILES]; // (flag<<32)|sum

#define FLAG_PARTIAL   1ull
#define FLAG_INCLUSIVE 2ull

// ---------------- mark presence bits + dup detection + extras count
// no early return: keep full warps converged for the aggregated ballot
__global__ void mark_kernel(const int4* __restrict__ coords, int n) {
    int i = blockIdx.x * blockDim.x + threadIdx.x;
    bool isextra = false;
    if (i < n) {
        int4 c = coords[i];
        unsigned int k = ((unsigned)((c.x * SDIM + c.y) * SDIM + c.z)) * SDIM + (unsigned)c.w;
        g_keys[i] = k;
        unsigned int bit = 1u << (k & 31);
        unsigned int old = atomicOr(&g_bitmap[k >> 5], bit);
        if (old & bit) {
            atomicOr(&g_dup[k >> 5], bit);   // second+ arrival
            isextra = true;
        }
    }
    unsigned int m = __ballot_sync(0xFFFFFFFFu, isextra);
    if ((threadIdx.x & 31) == 0 && m)
        atomicAdd(&g_extras, (unsigned)__popc(m));
}

// --- single-pass scan (decoupled lookback) + packed meta + dup/pad zeroing.
// Also restores g_bitmap/g_dup to zero for the next replay.
__global__ void scan_fused_kernel(float4* __restrict__ out, int n) {
    __shared__ unsigned int sh_warp[32];
    __shared__ unsigned int sh_tile;
    __shared__ unsigned int sh_offset;

    unsigned int tid  = threadIdx.x;
    unsigned int lane = tid & 31, wid = tid >> 5;

    if (tid == 0) sh_tile = atomicAdd(&g_tilecounter, 1u);
    __syncthreads();
    unsigned int tile = sh_tile;
    unsigned int gid  = tile * SCAN_TPB + tid;

    unsigned int w = g_bitmap[gid];
    unsigned int d = g_dup[gid];
    unsigned int v = __popc(w);

    // self-clean for next graph replay (values now live in registers)
    g_bitmap[gid] = 0u;
    g_dup[gid]    = 0u;

    // -------- pad-row zeroing (independent of scan result):
    // rows [n - extras, n) are padding; thread gid zeroes one full row
    {
        unsigned int extras = g_extras;
        if (gid < extras) {
            float4* p = out + (size_t)((unsigned)n - extras + gid) * (CCH / 4);
            #pragma unroll
            for (int j = 0; j < CCH / 4; j++)
                __stcs(p + j, make_float4(0.f, 0.f, 0.f, 0.f));
        }
    }

    // warp inclusive scan
    unsigned int inc = v;
    #pragma unroll
    for (int o = 1; o < 32; o <<= 1) {
        unsigned int t = __shfl_up_sync(0xFFFFFFFFu, inc, o);
        if (lane >= o) inc += t;
    }
    if (lane == 31) sh_warp[wid] = inc;
    __syncthreads();

    // warp 0 scans the 32 warp sums (exclusive)
    if (wid == 0) {
        unsigned int s = sh_warp[lane];
        unsigned int si = s;
        #pragma unroll
        for (int o = 1; o < 32; o <<= 1) {
            unsigned int t = __shfl_up_sync(0xFFFFFFFFu, si, o);
            if (lane >= o) si += t;
        }
        sh_warp[lane] = si - s;                 // exclusive warp offset
        if (lane == 31) {
            unsigned int blocktotal = si;
            if (tile == 0) {
                __threadfence();
                g_tilestate[tile] = (FLAG_INCLUSIVE << 32) | blocktotal;
                sh_offset = 0u;
            } else {
                __threadfence();
                g_tilestate[tile] = (FLAG_PARTIAL << 32) | blocktotal;
                unsigned int offset = 0;
                int j = (int)tile - 1;
                while (j >= 0) {
                    unsigned long long st = g_tilestate[j];
                    unsigned long long flag = st >> 32;
                    if (flag == FLAG_INCLUSIVE) { offset += (unsigned int)st; break; }
                    if (flag == FLAG_PARTIAL)   { offset += (unsigned int)st; j--; continue; }
                }
                __threadfence();
                g_tilestate[tile] = (FLAG_INCLUSIVE << 32) | (offset + blocktotal);
                sh_offset = offset;
            }
        }
    }
    __syncthreads();

    unsigned int pfx = sh_offset + sh_warp[wid] + inc - v;   // exclusive
    g_meta[gid] = make_uint4(w, pfx, d, 0u);

    // -------- dup-row zeroing: everything needed is already in registers
    while (d) {
        int b = __ffs(d) - 1;
        d &= d - 1;
        unsigned int rank = pfx + __popc(w & ((1u << b) - 1u));
        float4* p = out + (size_t)rank * (CCH / 4);
        #pragma unroll
        for (int j = 0; j < CCH / 4; j++)
            __stcs(p + j, make_float4(0.f, 0.f, 0.f, 0.f));
    }
}

// ------------------------------------------------------- scatter features
// 8 threads per point, one float4 channel-segment each.
// Also restores scan bookkeeping to zero for the next replay.
__global__ void scatter_kernel(const float4* __restrict__ feats,
                               float* __restrict__ out, int n) {
    int t = blockIdx.x * blockDim.x + threadIdx.x;

    // self-clean scan state (scan has fully retired; stream-ordered)
    if (t < SCAN_TILES) g_tilestate[t] = 0ull;
    if (t == SCAN_TILES) { g_tilecounter = 0u; g_extras = 0u; }

    if (t >= n * 8) return;
    int i = t >> 3;
    int g = t & 7;
    unsigned int k = g_keys[i];
    unsigned int w = k >> 5;
    unsigned int b = k & 31;
    uint4 m = __ldg(&g_meta[w]);               // {bitmap, pfx, dup, 0}
    unsigned int rank = m.y + __popc(m.x & ((1u << b) - 1u));
    bool isdup = (m.z >> b) & 1u;
    float4 f = __ldcs(feats + i * 8 + g);
    float* dst = out + (size_t)rank * CCH + g * 4;
    if (isdup) {
        atomicAdd(dst + 0, f.x);
        atomicAdd(dst + 1, f.y);
        atomicAdd(dst + 2, f.z);
        atomicAdd(dst + 3, f.w);
    } else {
        __stcs((float4*)dst, f);
    }
}

extern "C" void kernel_launch(void* const* d_in, const int* in_sizes, int n_in,
                              void* d_out, int out_size) {
    const int4*   coords = (const int4*)d_in[0];
    const float4* feats  = (const float4*)d_in[1];
    float*        out    = (float*)d_out;
    int n = in_sizes[0] / 4;

    mark_kernel<<<(n + 255) / 256, 256>>>(coords, n);
    scan_fused_kernel<<<SCAN_TILES, SCAN_TPB>>>((float4*)d_out, n);
    scatter_kernel<<<(n * 8 + 255) / 256, 256>>>(feats, out, n);
}

// round 14
// speedup vs baseline: 1.0994x; 1.0994x over previous
#include <cuda_runtime.h>
#include <stdint.h>

#define SDIM 64
#define CCH 32
#define KEYSPACE (SDIM*SDIM*SDIM*SDIM)   // 16,777,216
#define NWORDS (KEYSPACE/32)             // 524,288
#define SCAN_TPB 1024
#define SCAN_TILES (NWORDS / SCAN_TPB)   // 512
#define NMAX (1<<20)
#define MARK_PPT 4                        // points per thread in mark

__device__ unsigned int g_bitmap[NWORDS];
__device__ unsigned int g_dup[NWORDS];
__device__ uint4        g_meta[NWORDS];     // {bitmap, wordpfx, dup, 0}
__device__ unsigned int g_keys[NMAX];
__device__ unsigned int g_extras;           // n - unique
__device__ unsigned int g_tilecounter;
__device__ volatile unsigned long long g_tilestate[SCAN_TILES]; // (flag<<32)|sum

#define FLAG_PARTIAL   1ull
#define FLAG_INCLUSIVE 2ull

// ---------- zero bitmaps + scan state; also WARMS the bitmaps into L2 so
// mark's atomicOr RMWs hit L2 (~250cyc) instead of DRAM (~600cyc).
__global__ void zero_state_kernel() {
    int i = blockIdx.x * blockDim.x + threadIdx.x;
    if (i < NWORDS / 4) {
        ((uint4*)g_bitmap)[i] = make_uint4(0u, 0u, 0u, 0u);
        ((uint4*)g_dup)[i]    = make_uint4(0u, 0u, 0u, 0u);
    }
    if (i < SCAN_TILES) g_tilestate[i] = 0ull;
    if (i == 0) { g_tilecounter = 0u; g_extras = 0u; }
}

// ---------------- mark: 4 points per thread -> 4 independent atomic chains
__global__ void mark_kernel(const int4* __restrict__ coords, int n) {
    int base = (blockIdx.x * blockDim.x + threadIdx.x) * MARK_PPT;
    unsigned int extras = 0;

    int4 c[MARK_PPT];
    #pragma unroll
    for (int j = 0; j < MARK_PPT; j++)
        if (base + j < n) c[j] = coords[base + j];

    unsigned int k[MARK_PPT], bit[MARK_PPT], old[MARK_PPT];
    #pragma unroll
    for (int j = 0; j < MARK_PPT; j++) {
        if (base + j < n) {
            k[j] = ((unsigned)((c[j].x * SDIM + c[j].y) * SDIM + c[j].z)) * SDIM + (unsigned)c[j].w;
            g_keys[base + j] = k[j];
            bit[j] = 1u << (k[j] & 31);
            old[j] = atomicOr(&g_bitmap[k[j] >> 5], bit[j]);   // independent; MLP=4
        }
    }
    #pragma unroll
    for (int j = 0; j < MARK_PPT; j++) {
        if (base + j < n && (old[j] & bit[j])) {
            atomicOr(&g_dup[k[j] >> 5], bit[j]);   // second+ arrival (~3%)
            extras++;
        }
    }

    // warp-aggregated extras count: one atomic per warp
    #pragma unroll
    for (int o = 16; o; o >>= 1)
        extras += __shfl_down_sync(0xFFFFFFFFu, extras, o);
    if ((threadIdx.x & 31) == 0 && extras)
        atomicAdd(&g_extras, extras);
}

// --- single-pass scan (decoupled lookback) + packed meta + dup/pad zeroing
__global__ void scan_fused_kernel(float4* __restrict__ out, int n) {
    __shared__ unsigned int sh_warp[32];
    __shared__ unsigned int sh_tile;
    __shared__ unsigned int sh_offset;

    unsigned int tid  = threadIdx.x;
    unsigned int lane = tid & 31, wid = tid >> 5;

    if (tid == 0) sh_tile = atomicAdd(&g_tilecounter, 1u);
    __syncthreads();
    unsigned int tile = sh_tile;
    unsigned int gid  = tile * SCAN_TPB + tid;

    unsigned int w = g_bitmap[gid];
    unsigned int d = g_dup[gid];
    unsigned int v = __popc(w);

    // -------- pad-row zeroing (independent of scan result):
    // rows [n - extras, n) are padding; thread gid zeroes one full row
    {
        unsigned int extras = g_extras;
        if (gid < extras) {
            float4* p = out + (size_t)((unsigned)n - extras + gid) * (CCH / 4);
            #pragma unroll
            for (int j = 0; j < CCH / 4; j++)
                __stcs(p + j, make_float4(0.f, 0.f, 0.f, 0.f));
        }
    }

    // warp inclusive scan
    unsigned int inc = v;
    #pragma unroll
    for (int o = 1; o < 32; o <<= 1) {
        unsigned int t = __shfl_up_sync(0xFFFFFFFFu, inc, o);
        if (lane >= o) inc += t;
    }
    if (lane == 31) sh_warp[wid] = inc;
    __syncthreads();

    // warp 0 scans the 32 warp sums (exclusive)
    if (wid == 0) {
        unsigned int s = sh_warp[lane];
        unsigned int si = s;
        #pragma unroll
        for (int o = 1; o < 32; o <<= 1) {
            unsigned int t = __shfl_up_sync(0xFFFFFFFFu, si, o);
            if (lane >= o) si += t;
        }
        sh_warp[lane] = si - s;                 // exclusive warp offset
        if (lane == 31) {
            unsigned int blocktotal = si;
            if (tile == 0) {
                __threadfence();
                g_tilestate[tile] = (FLAG_INCLUSIVE << 32) | blocktotal;
                sh_offset = 0u;
            } else {
                __threadfence();
                g_tilestate[tile] = (FLAG_PARTIAL << 32) | blocktotal;
                unsigned int offset = 0;
                int j = (int)tile - 1;
                while (j >= 0) {
                    unsigned long long st = g_tilestate[j];
                    unsigned long long flag = st >> 32;
                    if (flag == FLAG_INCLUSIVE) { offset += (unsigned int)st; break; }
                    if (flag == FLAG_PARTIAL)   { offset += (unsigned int)st; j--; continue; }
                }
                __threadfence();
                g_tilestate[tile] = (FLAG_INCLUSIVE << 32) | (offset + blocktotal);
                sh_offset = offset;
            }
        }
    }
    __syncthreads();

    unsigned int pfx = sh_offset + sh_warp[wid] + inc - v;   // exclusive
    g_meta[gid] = make_uint4(w, pfx, d, 0u);

    // -------- dup-row zeroing: everything needed is already in registers
    while (d) {
        int b = __ffs(d) - 1;
        d &= d - 1;
        unsigned int rank = pfx + __popc(w & ((1u << b) - 1u));
        float4* p = out + (size_t)rank * (CCH / 4);
        #pragma unroll
        for (int j = 0; j < CCH / 4; j++)
            __stcs(p + j, make_float4(0.f, 0.f, 0.f, 0.f));
    }
}

// ------------------------------------------------------- scatter features
// 8 threads per point, one float4 channel-segment each
__global__ void scatter_kernel(const float4* __restrict__ feats,
                               float* __restrict__ out, int n) {
    int t = blockIdx.x * blockDim.x + threadIdx.x;
    if (t >= n * 8) return;
    int i = t >> 3;
    int g = t & 7;
    unsigned int k = g_keys[i];
    unsigned int w = k >> 5;
    unsigned int b = k & 31;
    uint4 m = __ldg(&g_meta[w]);               // {bitmap, pfx, dup, 0}
    unsigned int rank = m.y + __popc(m.x & ((1u << b) - 1u));
    bool isdup = (m.z >> b) & 1u;
    float4 f = __ldcs(feats + i * 8 + g);
    float* dst = out + (size_t)rank * CCH + g * 4;
    if (isdup) {
        atomicAdd(dst + 0, f.x);
        atomicAdd(dst + 1, f.y);
        atomicAdd(dst + 2, f.z);
        atomicAdd(dst + 3, f.w);
    } else {
        __stcs((float4*)dst, f);
    }
}

extern "C" void kernel_launch(void* const* d_in, const int* in_sizes, int n_in,
                              void* d_out, int out_size) {
    const int4*   coords = (const int4*)d_in[0];
    const float4* feats  = (const float4*)d_in[1];
    float*        out    = (float*)d_out;
    int n = in_sizes[0] / 4;

    zero_state_kernel<<<(NWORDS / 4 + 255) / 256, 256>>>();
    int mthreads = (n + MARK_PPT - 1) / MARK_PPT;
    mark_kernel<<<(mthreads + 255) / 256, 256>>>(coords, n);
    scan_fused_kernel<<<SCAN_TILES, SCAN_TPB>>>((float4*)d_out, n);
    scatter_kernel<<<(n * 8 + 255) / 256, 256>>>(feats, out, n);
}